// round 5
// baseline (speedup 1.0000x reference)
#include <cuda_runtime.h>
#include <math.h>

#define NB 8
#define NT 8192
#define ND 2048
#define NROWS (NB * NT)
#define KSEL 2048   // NT * 0.25

// Scratch + counters (no allocations allowed; device globals are sanctioned).
// Counters are reset by their consumer before kernel exit -> graph-replay safe.
__device__ float  d_Dst[NROWS];
__device__ float  d_Dch[NROWS];
__device__ double d_ma;
__device__ int    d_ctr1;
__device__ int    d_ctr2[NB];

// ---------------------------------------------------------------------------
// Kernel 1: per-row squared-norm reductions (warp-per-row, deep MLP, at the
// LTS/HBM cap: this reads the full 1.07 GB and IS the runtime) + fused global
// mean in the last-arriving CTA (threadFenceReduction pattern).
// Mean uses fp32 presums of 8-value groups accumulated in fp64, fixed order:
// deterministic; |error| ~1e-8 relative, and an error in ma shifts every CU
// identically (monotone) -> cannot change top-k ordering.
// ---------------------------------------------------------------------------
__global__ void __launch_bounds__(256) row_reduce_kernel(
    const float4* __restrict__ a, const float4* __restrict__ p)
{
    const int warp = threadIdx.x >> 5;
    const int lane = threadIdx.x & 31;
    const int row  = blockIdx.x * 8 + warp;
    const size_t base = (size_t)row * (ND / 4);

    float s_st = 0.0f, s_ch = 0.0f;
#pragma unroll
    for (int j = 0; j < 16; ++j) {
        const size_t idx = base + lane + 32 * j;
        float4 av = __ldg(&a[idx]);
        float4 pv = __ldg(&p[idx]);
        s_st += av.x * av.x + av.y * av.y + av.z * av.z + av.w * av.w;
        float dx = av.x - pv.x, dy = av.y - pv.y;
        float dz = av.z - pv.z, dw = av.w - pv.w;
        s_ch += dx * dx + dy * dy + dz * dz + dw * dw;
    }

#pragma unroll
    for (int off = 16; off > 0; off >>= 1) {
        s_st += __shfl_down_sync(0xFFFFFFFFu, s_st, off);
        s_ch += __shfl_down_sync(0xFFFFFFFFu, s_ch, off);
    }

    if (lane == 0) {
        const float invd = 1.0f / (float)ND;
        d_Dst[row] = s_st * invd;
        d_Dch[row] = s_ch * invd;
    }

    // ---- last-CTA global mean ----
    __shared__ int s_last;
    __threadfence();
    __syncthreads();
    if (threadIdx.x == 0)
        s_last = (atomicAdd(&d_ctr1, 1) == (int)gridDim.x - 1);
    __syncthreads();
    if (!s_last) return;
    __threadfence();  // acquire side of the fence/atomic handshake

    const int t = threadIdx.x;
    double acc[4] = {0.0, 0.0, 0.0, 0.0};
#pragma unroll
    for (int j = 0; j < 8; ++j) {
#pragma unroll
        for (int q = 0; q < 4; ++q) {
            float f = 0.0f;
#pragma unroll
            for (int r = 0; r < 8; ++r)
                f += __ldcg(&d_Dst[t + ((j * 4 + q) * 8 + r) * 256]);
            acc[q] += (double)f;
        }
    }
    double s = (acc[0] + acc[1]) + (acc[2] + acc[3]);
#pragma unroll
    for (int off = 16; off > 0; off >>= 1)
        s += __shfl_down_sync(0xFFFFFFFFu, s, off);
    __shared__ double ws[8];
    if (lane == 0) ws[warp] = s;
    __syncthreads();
    if (t == 0) {
        double tot = 0.0;
#pragma unroll
        for (int i = 0; i < 8; ++i) tot += ws[i];
        d_ma = tot / (double)NROWS;
        d_ctr1 = 0;   // reset for next graph replay
    }
}

// ---------------------------------------------------------------------------
// Kernel 2: gate (fp64 for ordering fidelity: order-statistic gaps near the
// k-th largest g are ~1e-5; ordering flips vs the reference's top-k cost ~1%
// rel_err) fused with per-batch exact top-k radix select in the last-arriving
// CTA of each batch. 16 CTAs x 512 elements per batch spread the fp64 exp
// work across 128 SMs; the select CTA caches all 8192 key bits in registers
// (8/thread) so radix passes touch only smem/ALU — no L2 round trips.
// ---------------------------------------------------------------------------
__global__ void __launch_bounds__(1024) gate_select_kernel(
    const float* __restrict__ oce, const float* __restrict__ mcu,
    const float* __restrict__ bce, const float* __restrict__ bcu,
    float* __restrict__ out)
{
    const int b    = blockIdx.x >> 4;
    const int seg  = blockIdx.x & 15;
    const int t    = threadIdx.x;
    const int warp = t >> 5;
    const int lane = t & 31;

    // ---- gate phase: 512 elements per CTA ----
    {
        const double ma      = d_ma;
        const double log_oce = log((double)oce[0] + 1e-10);
        const double m       = (double)mcu[0];
        const double xce     = (double)bce[0];
        const double xcu     = (double)bcu[0];
        const double bce_p = fmax(xce, 0.0) + log1p(exp(-fabs(xce)));  // softplus
        const double bcu_p = fmax(xcu, 0.0) + log1p(exp(-fabs(xcu)));
        if (t < 512) {
            const int idx = b * NT + seg * 512 + t;
            const double dst = (double)d_Dst[idx];
            const double dch = (double)d_Dch[idx];
            const double CE = dst - (dch - log_oce);
            const double CU = dst - m * ma;
            const double sce = 1.0 / (1.0 + exp(-bce_p * CE));
            const double scu = 1.0 / (1.0 + exp(-bcu_p * CU));
            out[idx] = (float)(sce + scu - sce * scu);
        }
    }

    // ---- handshake: last CTA of this batch runs the select ----
    __shared__ int s_last;
    __threadfence();
    __syncthreads();
    if (t == 0)
        s_last = (atomicAdd(&d_ctr2[b], 1) == 15);
    __syncthreads();
    if (!s_last) return;
    __threadfence();
    if (t == 0) d_ctr2[b] = 0;   // reset for next graph replay

    // ---- select phase ----
    __shared__ int hist[32 * 256];   // warp-private rows, 32KB
    __shared__ int warp_tot[8];
    __shared__ unsigned s_pref;
    __shared__ int s_remk, s_ce;

    const float* gb = out + b * NT;
    unsigned uv[8];                  // whole batch cached: 1024 thr x 8 keys
#pragma unroll
    for (int it = 0; it < 8; ++it)
        uv[it] = __float_as_uint(__ldcg(&gb[t + it * 1024]));

    if (t == 0) { s_pref = 0u; s_remk = KSEL; s_ce = 0; }
#pragma unroll
    for (int i = 0; i < 8; ++i) hist[t + i * 1024] = 0;
    __syncthreads();

    for (int shift = 24; shift >= 0; shift -= 8) {
        const unsigned pref = s_pref;
        const int remk = s_remk;
        const unsigned msk = (shift == 24) ? 0u : (0xFFFFFFFFu << (shift + 8));

        // warp-aggregated counting into warp-private rows: no atomics
        int* myhist = hist + warp * 256;
#pragma unroll
        for (int it = 0; it < 8; ++it) {
            const unsigned u = uv[it];
            const bool ok = ((u & msk) == pref);
            const int bin = (u >> shift) & 0xFF;
            const unsigned active = __ballot_sync(0xFFFFFFFFu, ok);
            if (ok) {
                const unsigned peers = __match_any_sync(active, bin);
                if (lane == (__ffs(peers) - 1))
                    myhist[bin] += __popc(peers);
            }
        }
        __syncthreads();

        // fused row-sum + suffix scan: thread t owns bin r = 255 - t
        int v = 0, x = 0;
        if (t < 256) {
            const int bin = 255 - t;
#pragma unroll
            for (int w = 0; w < 32; ++w) v += hist[w * 256 + bin];
            x = v;
#pragma unroll
            for (int off = 1; off < 32; off <<= 1) {
                const int y = __shfl_up_sync(0xFFFFFFFFu, x, off);
                if (lane >= off) x += y;
            }
            if (lane == 31) warp_tot[warp] = x;
        }
        __syncthreads();
        if (t < 256) {
            int offset = 0;
            for (int w = 0; w < warp; ++w) offset += warp_tot[w];
            const int cum  = x + offset;   // count of bins >= r under prefix
            const int prev = cum - v;      // count of bins  > r
            if (prev < remk && cum >= remk) {     // exactly one winner
                s_pref = pref | ((unsigned)(255 - t) << shift);
                s_remk = remk - prev;
                if (shift == 0) s_ce = v;
            }
        }
        if (shift > 0) {                   // zero hist for next pass
#pragma unroll
            for (int i = 0; i < 8; ++i) hist[t + i * 1024] = 0;
        }
        __syncthreads();
    }

    const unsigned thresh = s_pref;   // exact bit pattern of k-th largest
    const int need_eq = s_remk;       // equal-to-threshold elements to accept
    const int c_eq = s_ce;            // equal-to-threshold elements present

    // write binary mask from register-cached keys
    float* mout = out + NROWS + b * NT;
#pragma unroll
    for (int it = 0; it < 8; ++it) {
        const int i = t + it * 1024;
        const unsigned u = uv[it];
        float mval;
        if (u > thresh)      mval = 1.0f;
        else if (u < thresh) mval = 0.0f;
        else if (c_eq == need_eq) mval = 1.0f;          // no over-tie (common)
        else {
            // rare exact fp32 tie at threshold: lower index wins (lax.top_k)
            int r = 0;
            for (int j = 0; j < i; ++j)
                if (__float_as_uint(__ldcg(&gb[j])) == thresh) ++r;
            mval = (r < need_eq) ? 1.0f : 0.0f;
        }
        mout[i] = mval;
    }
}

// ---------------------------------------------------------------------------
extern "C" void kernel_launch(void* const* d_in, const int* in_sizes, int n_in,
                              void* d_out, int out_size)
{
    const float4* a = (const float4*)d_in[0];   // actual_residual   [8,8192,2048] f32
    const float4* p = (const float4*)d_in[1];   // predicted_residual[8,8192,2048] f32
    const float* oce = (const float*)d_in[2];
    const float* mcu = (const float*)d_in[3];
    const float* bce = (const float*)d_in[4];
    const float* bcu = (const float*)d_in[5];
    float* out = (float*)d_out;                  // [2, 8, 8192]: g then binary mask

    row_reduce_kernel<<<NROWS / 8, 256>>>(a, p);
    gate_select_kernel<<<NB * 16, 1024>>>(oce, mcu, bce, bcu, out);
}

// round 6
// speedup vs baseline: 1.0597x; 1.0597x over previous
#include <cuda_runtime.h>
#include <math.h>

#define NB 8
#define NT 8192
#define ND 2048
#define NROWS (NB * NT)
#define KSEL 2048   // NT * 0.25

// Scratch + counters (device globals; no allocations). Counters reset by
// their consumer before kernel exit -> graph-replay safe.
__device__ double d_ea[NROWS];    // exp(-bce_p * CE)   per row
__device__ double d_eb0[NROWS];   // exp(-bcu_p * D_st) per row
__device__ double d_part[NROWS / 8];  // per-CTA fp64 partial sums of D_st
__device__ double d_K;            // exp(bcu_p * m * ma)
__device__ int    d_ctr1;
__device__ int    d_ctr2[NB];

// Fast double-precision exp: 13-term Taylor on r in [-ln2/2, ln2/2] after
// Cody-Waite reduction; ~1e-15 rel accuracy on [-700, 700] (clamped).
// ~18 DP instrs vs ~50 for libm exp. A 1e-15 perturbation of g cannot flip
// top-k ordering (adjacent order-statistic gaps are ~1e-5).
__device__ __forceinline__ double fast_exp(double x)
{
    x = fmin(fmax(x, -700.0), 700.0);
    const double LOG2E = 1.4426950408889634074;
    const double LN2HI = 6.93147180369123816490e-01;
    const double LN2LO = 1.90821492927058770002e-10;
    double k = rint(x * LOG2E);
    double r = fma(-k, LN2HI, x);
    r = fma(-k, LN2LO, r);
    double p = 2.08767569878681e-09;           // 1/12!
    p = fma(p, r, 2.50521083854417e-08);       // 1/11!
    p = fma(p, r, 2.75573192239859e-07);
    p = fma(p, r, 2.75573192239859e-06);
    p = fma(p, r, 2.48015873015873e-05);
    p = fma(p, r, 1.98412698412698e-04);
    p = fma(p, r, 1.38888888888889e-03);
    p = fma(p, r, 8.33333333333333e-03);
    p = fma(p, r, 4.16666666666667e-02);
    p = fma(p, r, 1.66666666666667e-01);
    p = fma(p, r, 0.5);
    p = fma(p, r, 1.0);
    p = fma(p, r, 1.0);
    long long ki = (long long)k;
    double s = __longlong_as_double((unsigned long long)(ki + 1023) << 52);
    return p * s;
}

// ---------------------------------------------------------------------------
// Kernel 1: per-row squared-norm reductions (warp-per-row, at the LTS/HBM
// cap: reads the full 1.07 GB and IS the runtime), with the per-row fp64
// exps computed in a one-warp CTA tail (8 rows in 8 lanes) -- ~22us of DP
// pipe chip-wide, hidden under ~155us of memory stalls. Last-arriving CTA
// computes the global mean from per-CTA fp64 partials and the scalar K.
// ---------------------------------------------------------------------------
__global__ void __launch_bounds__(256) row_reduce_kernel(
    const float4* __restrict__ a, const float4* __restrict__ p,
    const float* __restrict__ oce, const float* __restrict__ mcu,
    const float* __restrict__ bce, const float* __restrict__ bcu)
{
    const int warp = threadIdx.x >> 5;
    const int lane = threadIdx.x & 31;
    const int row  = blockIdx.x * 8 + warp;
    const size_t base = (size_t)row * (ND / 4);

    float s_st = 0.0f, s_ch = 0.0f;
#pragma unroll
    for (int j = 0; j < 16; ++j) {
        const size_t idx = base + lane + 32 * j;
        float4 av = __ldg(&a[idx]);
        float4 pv = __ldg(&p[idx]);
        s_st += av.x * av.x + av.y * av.y + av.z * av.z + av.w * av.w;
        float dx = av.x - pv.x, dy = av.y - pv.y;
        float dz = av.z - pv.z, dw = av.w - pv.w;
        s_ch += dx * dx + dy * dy + dz * dz + dw * dw;
    }

#pragma unroll
    for (int off = 16; off > 0; off >>= 1) {
        s_st += __shfl_down_sync(0xFFFFFFFFu, s_st, off);
        s_ch += __shfl_down_sync(0xFFFFFFFFu, s_ch, off);
    }

    __shared__ float sh_dst[8], sh_dch[8];
    if (lane == 0) {
        const float invd = 1.0f / (float)ND;
        sh_dst[warp] = s_st * invd;
        sh_dch[warp] = s_ch * invd;
    }
    __syncthreads();

    // ---- CTA tail: one warp, 8 active lanes, computes the 2 fp64 exps per
    // row and this CTA's fp64 partial sum of D_st. Scalars in fp32 (cheap;
    // reference computes them in fp32 too; effect on g ordering ~1e-9).
    if (threadIdx.x < 8) {
        const float xce = bce[0], xcu = bcu[0];
        const float bce_p = fmaxf(xce, 0.0f) + log1pf(expf(-fabsf(xce)));
        const float bcu_p = fmaxf(xcu, 0.0f) + log1pf(expf(-fabsf(xcu)));
        const float logoce = logf(oce[0] + 1e-10f);

        const int r = blockIdx.x * 8 + threadIdx.x;
        const double dst = (double)sh_dst[threadIdx.x];
        const double dch = (double)sh_dch[threadIdx.x];
        const double CE = dst - (dch - (double)logoce);
        d_ea[r]  = fast_exp(-(double)bce_p * CE);
        d_eb0[r] = fast_exp(-(double)bcu_p * dst);

        if (threadIdx.x == 0) {
            double ps = 0.0;
#pragma unroll
            for (int i = 0; i < 8; ++i) ps += (double)sh_dst[i];
            d_part[blockIdx.x] = ps;
        }
    }

    // ---- last-CTA: global mean of D_st -> scalar K ----
    __shared__ int s_last;
    __threadfence();
    __syncthreads();
    if (threadIdx.x == 0)
        s_last = (atomicAdd(&d_ctr1, 1) == (int)gridDim.x - 1);
    __syncthreads();
    if (!s_last) return;
    __threadfence();   // acquire side of the handshake

    const int t = threadIdx.x;
    double a0 = 0.0, a1 = 0.0, a2 = 0.0, a3 = 0.0;
#pragma unroll
    for (int j = 0; j < 8; ++j) {
        a0 += __ldcg(&d_part[t + (4 * j + 0) * 256]);
        a1 += __ldcg(&d_part[t + (4 * j + 1) * 256]);
        a2 += __ldcg(&d_part[t + (4 * j + 2) * 256]);
        a3 += __ldcg(&d_part[t + (4 * j + 3) * 256]);
    }
    double s = (a0 + a1) + (a2 + a3);
#pragma unroll
    for (int off = 16; off > 0; off >>= 1)
        s += __shfl_down_sync(0xFFFFFFFFu, s, off);
    __shared__ double ws[8];
    if (lane == 0) ws[warp] = s;
    __syncthreads();
    if (t == 0) {
        double tot = 0.0;
#pragma unroll
        for (int i = 0; i < 8; ++i) tot += ws[i];
        const double ma = tot / (double)NROWS;
        const float xcu = bcu[0];
        const float bcu_p = fmaxf(xcu, 0.0f) + log1pf(expf(-fabsf(xcu)));
        d_K = fast_exp((double)bcu_p * (double)mcu[0] * ma);
        d_ctr1 = 0;   // reset for next graph replay
    }
}

// ---------------------------------------------------------------------------
// Kernel 2: gate (now exp-free: g = (1+ea+eb)/(1+ea+eb+ea*eb), eb = eb0*K;
// ~6 DP ops + 1 div per element) fused with per-batch exact top-k radix
// select in the last-arriving CTA of each batch (16 CTAs x 512 elem/batch).
// Select CTA caches all 8192 keys in registers; warp-aggregated histograms,
// no atomics; 3 barriers per pass.
// ---------------------------------------------------------------------------
__global__ void __launch_bounds__(1024) gate_select_kernel(float* __restrict__ out)
{
    const int b    = blockIdx.x >> 4;
    const int seg  = blockIdx.x & 15;
    const int t    = threadIdx.x;
    const int warp = t >> 5;
    const int lane = t & 31;

    // ---- gate phase: 512 elements per CTA, exp-free fp64 ----
    if (t < 512) {
        const double K = d_K;
        const int idx = b * NT + seg * 512 + t;
        const double ea  = d_ea[idx];
        const double eb  = d_eb0[idx] * K;
        const double num = 1.0 + ea + eb;
        out[idx] = (float)(num / (num + ea * eb));
    }

    // ---- handshake: last CTA of this batch runs the select ----
    __shared__ int s_last;
    __threadfence();
    __syncthreads();
    if (t == 0)
        s_last = (atomicAdd(&d_ctr2[b], 1) == 15);
    __syncthreads();
    if (!s_last) return;
    __threadfence();
    if (t == 0) d_ctr2[b] = 0;   // reset for next graph replay

    // ---- select phase: exact top-k radix select on fp32 bit patterns ----
    __shared__ int hist[32 * 256];   // warp-private rows, 32KB
    __shared__ int warp_tot[8];
    __shared__ unsigned s_pref;
    __shared__ int s_remk, s_ce;

    const float* gb = out + b * NT;
    unsigned uv[8];                  // whole batch cached: 1024 thr x 8 keys
#pragma unroll
    for (int it = 0; it < 8; ++it)
        uv[it] = __float_as_uint(__ldcg(&gb[t + it * 1024]));

    if (t == 0) { s_pref = 0u; s_remk = KSEL; s_ce = 0; }
#pragma unroll
    for (int i = 0; i < 8; ++i) hist[t + i * 1024] = 0;
    __syncthreads();

    for (int shift = 24; shift >= 0; shift -= 8) {
        const unsigned pref = s_pref;
        const int remk = s_remk;
        const unsigned msk = (shift == 24) ? 0u : (0xFFFFFFFFu << (shift + 8));

        int* myhist = hist + warp * 256;
#pragma unroll
        for (int it = 0; it < 8; ++it) {
            const unsigned u = uv[it];
            const bool ok = ((u & msk) == pref);
            const int bin = (u >> shift) & 0xFF;
            const unsigned active = __ballot_sync(0xFFFFFFFFu, ok);
            if (ok) {
                const unsigned peers = __match_any_sync(active, bin);
                if (lane == (__ffs(peers) - 1))
                    myhist[bin] += __popc(peers);
            }
        }
        __syncthreads();

        // fused row-sum + suffix scan: thread t owns bin r = 255 - t
        int v = 0, x = 0;
        if (t < 256) {
            const int bin = 255 - t;
#pragma unroll
            for (int w = 0; w < 32; ++w) v += hist[w * 256 + bin];
            x = v;
#pragma unroll
            for (int off = 1; off < 32; off <<= 1) {
                const int y = __shfl_up_sync(0xFFFFFFFFu, x, off);
                if (lane >= off) x += y;
            }
            if (lane == 31) warp_tot[warp] = x;
        }
        __syncthreads();
        if (t < 256) {
            int offset = 0;
            for (int w = 0; w < warp; ++w) offset += warp_tot[w];
            const int cum  = x + offset;   // count of bins >= r under prefix
            const int prev = cum - v;      // count of bins  > r
            if (prev < remk && cum >= remk) {     // exactly one winner
                s_pref = pref | ((unsigned)(255 - t) << shift);
                s_remk = remk - prev;
                if (shift == 0) s_ce = v;
            }
        }
        if (shift > 0) {                   // zero hist for next pass
#pragma unroll
            for (int i = 0; i < 8; ++i) hist[t + i * 1024] = 0;
        }
        __syncthreads();
    }

    const unsigned thresh = s_pref;   // exact bit pattern of k-th largest
    const int need_eq = s_remk;       // equal-to-threshold elements to accept
    const int c_eq = s_ce;            // equal-to-threshold elements present

    float* mout = out + NROWS + b * NT;
#pragma unroll
    for (int it = 0; it < 8; ++it) {
        const int i = t + it * 1024;
        const unsigned u = uv[it];
        float mval;
        if (u > thresh)      mval = 1.0f;
        else if (u < thresh) mval = 0.0f;
        else if (c_eq == need_eq) mval = 1.0f;          // no over-tie (common)
        else {
            // rare exact fp32 tie at threshold: lower index wins (lax.top_k)
            int r = 0;
            for (int j = 0; j < i; ++j)
                if (__float_as_uint(__ldcg(&gb[j])) == thresh) ++r;
            mval = (r < need_eq) ? 1.0f : 0.0f;
        }
        mout[i] = mval;
    }
}

// ---------------------------------------------------------------------------
extern "C" void kernel_launch(void* const* d_in, const int* in_sizes, int n_in,
                              void* d_out, int out_size)
{
    const float4* a = (const float4*)d_in[0];   // actual_residual   [8,8192,2048] f32
    const float4* p = (const float4*)d_in[1];   // predicted_residual[8,8192,2048] f32
    const float* oce = (const float*)d_in[2];
    const float* mcu = (const float*)d_in[3];
    const float* bce = (const float*)d_in[4];
    const float* bcu = (const float*)d_in[5];
    float* out = (float*)d_out;                  // [2, 8, 8192]: g then binary mask

    row_reduce_kernel<<<NROWS / 8, 256>>>(a, p, oce, mcu, bce, bcu);
    gate_select_kernel<<<NB * 16, 1024>>>(out);
}